// round 2
// baseline (speedup 1.0000x reference)
#include <cuda_runtime.h>

// Problem constants
#define Bn   4
#define Hq   512
#define Wq   512
#define Cn   128
#define Hon  502
#define Won  502
#define OFFS 2
// Tiling
#define TH   8      // output rows per block
#define TW   64     // output cols per block
#define WT   4      // output cols per thread
#define CCK  8      // channel chunk
#define QW   72     // TW + 8 (halo)
#define QR   10     // q rows per dy-group: TH + 2
#define PPAD 68     // padded p width (conflict-free STS, 16B-aligned LDS.128)
#define QPAD 76     // padded q width
#define NTX  16
#define NTY  8
#define NTHR 128

__global__ __launch_bounds__(NTHR, 3)
void corr9x9_kernel(const float* __restrict__ pg,
                    const float* __restrict__ qg,
                    float* __restrict__ outg)
{
    __shared__ __align__(16) float p_s[TH][CCK][PPAD];
    __shared__ __align__(16) float q_s[QR][CCK][QPAD];

    const int tx  = threadIdx.x;
    const int ty  = threadIdx.y;
    const int tid = ty * NTX + tx;

    const int wo0 = blockIdx.x * TW;
    const int ho0 = blockIdx.y * TH;
    const int b   = blockIdx.z;

    const float* pb = pg + (size_t)b * Hon * Won * Cn;
    const float* qb = qg + (size_t)b * Hq  * Wq  * Cn;

    const int ho = ho0 + ty;

    // 3 dy-groups of 3 dy each
    for (int g = 0; g < 3; ++g) {
        float acc[WT][3][9];
        #pragma unroll
        for (int i = 0; i < WT; ++i)
            #pragma unroll
            for (int d = 0; d < 3; ++d)
                #pragma unroll
                for (int dx = 0; dx < 9; ++dx)
                    acc[i][d][dx] = 0.0f;

        const int r0 = ho0 + 3 * g + OFFS;   // first q row for this dy-group

        for (int cc = 0; cc < Cn; cc += CCK) {
            __syncthreads();

            // ---- stage p chunk: [TH rows][TW cols][CCK ch], transposed to [row][c][w]
            // 8*64*2 = 1024 float4 loads, 128 threads -> 8 iters
            #pragma unroll
            for (int it = 0; it < (TH * TW * 2) / NTHR; ++it) {
                int flat = tid + it * NTHR;
                int c4   = flat & 1;
                int w    = (flat >> 1) & (TW - 1);
                int row  = flat >> 7;
                int hr   = ho0 + row; if (hr > Hon - 1) hr = Hon - 1;
                int wr   = wo0 + w;   if (wr > Won - 1) wr = Won - 1;
                const float4 v = *(const float4*)(pb + ((size_t)hr * Won + wr) * Cn + cc + c4 * 4);
                p_s[row][c4 * 4 + 0][w] = v.x;
                p_s[row][c4 * 4 + 1][w] = v.y;
                p_s[row][c4 * 4 + 2][w] = v.z;
                p_s[row][c4 * 4 + 3][w] = v.w;
            }

            // ---- stage q chunk: [QR rows][QW cols][CCK ch] -> [rr][c][w]
            // 10*72*2 = 1440 float4 loads -> 12 iters with guard
            #pragma unroll
            for (int it = 0; it < 12; ++it) {
                int flat = tid + it * NTHR;
                if (flat < QR * QW * 2) {
                    int c4 = flat & 1;
                    int t  = flat >> 1;
                    int w  = t % QW;
                    int rr = t / QW;
                    int hr = r0 + rr;           if (hr > Hq - 1) hr = Hq - 1;
                    int wr = wo0 + OFFS + w;    if (wr > Wq - 1) wr = Wq - 1;
                    const float4 v = *(const float4*)(qb + ((size_t)hr * Wq + wr) * Cn + cc + c4 * 4);
                    q_s[rr][c4 * 4 + 0][w] = v.x;
                    q_s[rr][c4 * 4 + 1][w] = v.y;
                    q_s[rr][c4 * 4 + 2][w] = v.z;
                    q_s[rr][c4 * 4 + 3][w] = v.w;
                }
            }

            __syncthreads();

            // ---- compute: per channel, 1 p-float4 + 9 q-float4 feed 108 FMAs
            for (int c = 0; c < CCK; ++c) {
                const float4 pv = *(const float4*)&p_s[ty][c][tx * WT];
                float pp[WT] = {pv.x, pv.y, pv.z, pv.w};
                #pragma unroll
                for (int d = 0; d < 3; ++d) {
                    float qv[12];
                    const float4 a0 = *(const float4*)&q_s[ty + d][c][tx * WT];
                    const float4 a1 = *(const float4*)&q_s[ty + d][c][tx * WT + 4];
                    const float4 a2 = *(const float4*)&q_s[ty + d][c][tx * WT + 8];
                    qv[0] = a0.x;  qv[1] = a0.y;  qv[2]  = a0.z;  qv[3]  = a0.w;
                    qv[4] = a1.x;  qv[5] = a1.y;  qv[6]  = a1.z;  qv[7]  = a1.w;
                    qv[8] = a2.x;  qv[9] = a2.y;  qv[10] = a2.z;  qv[11] = a2.w;
                    #pragma unroll
                    for (int i = 0; i < WT; ++i)
                        #pragma unroll
                        for (int dx = 0; dx < 9; ++dx)
                            acc[i][d][dx] = fmaf(pp[i], qv[i + dx], acc[i][d][dx]);
                }
            }
        }

        // ---- write this dy-group's outputs
        if (ho < Hon) {
            #pragma unroll
            for (int i = 0; i < WT; ++i) {
                int wo = wo0 + tx * WT + i;
                if (wo < Won) {
                    #pragma unroll
                    for (int d = 0; d < 3; ++d) {
                        size_t base = ((((size_t)b * Hon + ho) * Won + wo) * 9 + (3 * g + d)) * 9;
                        #pragma unroll
                        for (int dx = 0; dx < 9; ++dx)
                            outg[base + dx] = acc[i][d][dx];
                    }
                }
            }
        }
    }
}

extern "C" void kernel_launch(void* const* d_in, const int* in_sizes, int n_in,
                              void* d_out, int out_size)
{
    const float* p = (const float*)d_in[0];
    const float* q = (const float*)d_in[1];
    float* out = (float*)d_out;

    dim3 block(NTX, NTY);
    dim3 grid((Won + TW - 1) / TW,   // 8
              (Hon + TH - 1) / TH,   // 63
              Bn);                   // 4
    corr9x9_kernel<<<grid, block>>>(p, q, out);
}